// round 6
// baseline (speedup 1.0000x reference)
#include <cuda_runtime.h>
#include <cuda_bf16.h>
#include <math.h>
#include <stdint.h>

#define N_NODES 20000
#define N_EDGES 160000
#define F_IN   512
#define F_HID  256
#define F_OUT  512
#define NH     8
#define NEG_SLOPE 0.2f

// ---------------- scratch (device globals; allocation-free) ----------------
__device__ float g_feat[(size_t)N_NODES * NH * F_OUT];
__device__ float g_agg [(size_t)N_NODES * NH * F_HID];
__device__ float g_h   [(size_t)N_NODES * F_HID];
__device__ float g_Wt  [1 << 20];
__device__ float g_el  [N_NODES * NH];
__device__ float g_er  [N_NODES * NH];
__device__ int   g_cnt [N_NODES];
__device__ int   g_rs  [N_NODES];
__device__ int   g_cur [N_NODES];
__device__ int   g_csrc[N_EDGES];        // CSR-ordered source node ids
__device__ int   g_bsum[64];

// =================== mma.sync bf16 split-3 GEMM ===================
// C[M,Nc] = A[M,K] @ W[K,Nc]; Wt[Nc,K] = W^T.
// Split: A = Ah+Al, B = Bh+Bl (bf16); D += Ah*Bh + Ah*Bl + Al*Bh.
// Block tile 128x128, BK=32, 8 warps (warp tile 64x32), m16n8k16.

#define ROWB 80           // smem row stride in bytes (20 words, ldmatrix conflict-free)
#define SM_AHI 0
#define SM_ALO (128 * ROWB)
#define SM_BHI (2 * 128 * ROWB)
#define SM_BLO (3 * 128 * ROWB)
#define SM_TOT (4 * 128 * ROWB)   // 40960 B

__device__ __forceinline__ uint32_t smem_u32(const void* p) {
    uint32_t a;
    asm("{ .reg .u64 t; cvta.to.shared.u64 t, %1; cvt.u32.u64 %0, t; }" : "=r"(a) : "l"(p));
    return a;
}
__device__ __forceinline__ void ldm_x4(uint32_t* r, uint32_t addr) {
    asm volatile("ldmatrix.sync.aligned.m8n8.x4.shared.b16 {%0,%1,%2,%3}, [%4];"
                 : "=r"(r[0]), "=r"(r[1]), "=r"(r[2]), "=r"(r[3]) : "r"(addr));
}
__device__ __forceinline__ void ldm_x2(uint32_t* r, uint32_t addr) {
    asm volatile("ldmatrix.sync.aligned.m8n8.x2.shared.b16 {%0,%1}, [%2];"
                 : "=r"(r[0]), "=r"(r[1]) : "r"(addr));
}
__device__ __forceinline__ void mma_bf16(float* d, const uint32_t* a, const uint32_t* b) {
    asm volatile(
        "mma.sync.aligned.m16n8k16.row.col.f32.bf16.bf16.f32 "
        "{%0,%1,%2,%3}, {%4,%5,%6,%7}, {%8,%9}, {%0,%1,%2,%3};"
        : "+f"(d[0]), "+f"(d[1]), "+f"(d[2]), "+f"(d[3])
        : "r"(a[0]), "r"(a[1]), "r"(a[2]), "r"(a[3]), "r"(b[0]), "r"(b[1]));
}

__device__ __forceinline__ void split_store(char* hp, char* lp, float4 v) {
    __nv_bfloat16 hx = __float2bfloat16_rn(v.x);
    __nv_bfloat16 hy = __float2bfloat16_rn(v.y);
    __nv_bfloat16 hz = __float2bfloat16_rn(v.z);
    __nv_bfloat16 hw = __float2bfloat16_rn(v.w);
    __nv_bfloat16 lx = __float2bfloat16_rn(v.x - __bfloat162float(hx));
    __nv_bfloat16 ly = __float2bfloat16_rn(v.y - __bfloat162float(hy));
    __nv_bfloat16 lz = __float2bfloat16_rn(v.z - __bfloat162float(hz));
    __nv_bfloat16 lw = __float2bfloat16_rn(v.w - __bfloat162float(hw));
    __nv_bfloat162 h0 = __nv_bfloat162(hx, hy), h1 = __nv_bfloat162(hz, hw);
    __nv_bfloat162 l0 = __nv_bfloat162(lx, ly), l1 = __nv_bfloat162(lz, lw);
    *(uint2*)hp = make_uint2(*(uint32_t*)&h0, *(uint32_t*)&h1);
    *(uint2*)lp = make_uint2(*(uint32_t*)&l0, *(uint32_t*)&l1);
}

__global__ void __launch_bounds__(256) k_gemm_mma(const float* __restrict__ A,
                                                  const float* __restrict__ Wt,
                                                  float* __restrict__ C,
                                                  int M, int K, int Nc) {
    __shared__ __align__(16) char sm[SM_TOT];
    const uint32_t smb = smem_u32(sm);

    const int tid  = threadIdx.x;
    const int wid  = tid >> 5;
    const int lane = tid & 31;
    const int m0 = blockIdx.y * 128;
    const int n0 = blockIdx.x * 128;
    const int wm = (wid >> 2) * 64;     // warp row offset (0/64)
    const int wn = (wid & 3) * 32;      // warp col offset (0/32/64/96)

    float acc[4][4][4] = {};
    const float4 z4 = make_float4(0.f, 0.f, 0.f, 0.f);

    const uint32_t aRow = wm + (lane & 15);
    const uint32_t aKof = (lane >> 4) * 16;
    const uint32_t bRow = wn + (lane & 7);
    const uint32_t bKof = ((lane >> 3) & 1) * 16;
    const uint32_t aHiAddr = smb + SM_AHI + aRow * ROWB + aKof;
    const uint32_t aLoAddr = smb + SM_ALO + aRow * ROWB + aKof;
    const uint32_t bHiAddr = smb + SM_BHI + bRow * ROWB + bKof;
    const uint32_t bLoAddr = smb + SM_BLO + bRow * ROWB + bKof;

    for (int k0 = 0; k0 < K; k0 += 32) {
        if (k0) __syncthreads();
        // ---- global -> smem with hi/lo split: A 128x32, B 128x32 ----
#pragma unroll
        for (int it = 0; it < 4; it++) {
            int idx = tid + (it << 8);            // 0..1023
            int r = idx >> 3;
            int c4 = (idx & 7) << 2;
            float4 v = (m0 + r < M) ? *(const float4*)&A[(size_t)(m0 + r) * K + k0 + c4] : z4;
            split_store(sm + SM_AHI + r * ROWB + c4 * 2,
                        sm + SM_ALO + r * ROWB + c4 * 2, v);
        }
#pragma unroll
        for (int it = 0; it < 4; it++) {
            int idx = tid + (it << 8);
            int r = idx >> 3;
            int c4 = (idx & 7) << 2;
            float4 v = *(const float4*)&Wt[(size_t)(n0 + r) * K + k0 + c4];
            split_store(sm + SM_BHI + r * ROWB + c4 * 2,
                        sm + SM_BLO + r * ROWB + c4 * 2, v);
        }
        __syncthreads();

        // ---- compute: 2 k-steps of m16n8k16 ----
#pragma unroll
        for (int ks = 0; ks < 2; ks++) {
            uint32_t ahi[4][4], alo[4][4];
#pragma unroll
            for (int mf = 0; mf < 4; mf++) {
                ldm_x4(ahi[mf], aHiAddr + mf * (16 * ROWB) + ks * 32);
                ldm_x4(alo[mf], aLoAddr + mf * (16 * ROWB) + ks * 32);
            }
#pragma unroll
            for (int nf = 0; nf < 4; nf++) {
                uint32_t bhi[2], blo[2];
                ldm_x2(bhi, bHiAddr + nf * (8 * ROWB) + ks * 32);
                ldm_x2(blo, bLoAddr + nf * (8 * ROWB) + ks * 32);
#pragma unroll
                for (int mf = 0; mf < 4; mf++) {
                    mma_bf16(acc[mf][nf], ahi[mf], bhi);
                    mma_bf16(acc[mf][nf], ahi[mf], blo);
                    mma_bf16(acc[mf][nf], alo[mf], bhi);
                }
            }
        }
    }

    // ---- epilogue ----
#pragma unroll
    for (int mf = 0; mf < 4; mf++) {
        int row0 = m0 + wm + mf * 16 + (lane >> 2);
#pragma unroll
        for (int nf = 0; nf < 4; nf++) {
            int col = n0 + wn + nf * 8 + (lane & 3) * 2;
            if (row0 < M)
                *(float2*)&C[(size_t)row0 * Nc + col] = make_float2(acc[mf][nf][0], acc[mf][nf][1]);
            if (row0 + 8 < M)
                *(float2*)&C[(size_t)(row0 + 8) * Nc + col] = make_float2(acc[mf][nf][2], acc[mf][nf][3]);
        }
    }
}

// ---------------- W transpose: Wt[n][k] = W[k][n] ----------------
__global__ void k_transpose(const float* __restrict__ W, float* __restrict__ Wt,
                            int K, int Nc) {
    __shared__ float tile[32][33];
    int n0 = blockIdx.x * 32, k0 = blockIdx.y * 32;
    int tx = threadIdx.x, ty = threadIdx.y;
#pragma unroll
    for (int j = 0; j < 32; j += 8)
        tile[ty + j][tx] = W[(size_t)(k0 + ty + j) * Nc + n0 + tx];
    __syncthreads();
#pragma unroll
    for (int j = 0; j < 32; j += 8)
        Wt[(size_t)(n0 + ty + j) * K + k0 + tx] = tile[tx][ty + j];
}

// ---------------- CSR build ----------------
__global__ void k_zero_cnt() {
    int i = blockIdx.x * blockDim.x + threadIdx.x;
    if (i < N_NODES) g_cnt[i] = 0;
}
__global__ void k_count(const int* __restrict__ dst) {
    int e = blockIdx.x * blockDim.x + threadIdx.x;
    if (e < N_EDGES) atomicAdd(&g_cnt[dst[e]], 1);
}
__global__ void k_scan_block() {
    __shared__ int s[512];
    int i = blockIdx.x * 512 + threadIdx.x;
    int v = (i < N_NODES) ? g_cnt[i] : 0;
    s[threadIdx.x] = v;
    __syncthreads();
    for (int off = 1; off < 512; off <<= 1) {
        int t = (threadIdx.x >= off) ? s[threadIdx.x - off] : 0;
        __syncthreads();
        s[threadIdx.x] += t;
        __syncthreads();
    }
    if (i < N_NODES) g_rs[i] = s[threadIdx.x] - v;
    if (threadIdx.x == 511) g_bsum[blockIdx.x] = s[511];
}
__global__ void k_scan_bsum(int nb) {
    if (threadIdx.x == 0 && blockIdx.x == 0) {
        int acc = 0;
        for (int i = 0; i < nb; i++) { int t = g_bsum[i]; g_bsum[i] = acc; acc += t; }
    }
}
__global__ void k_scan_add() {
    int i = blockIdx.x * 512 + threadIdx.x;
    if (i < N_NODES) {
        int v = g_rs[i] + g_bsum[blockIdx.x];
        g_rs[i]  = v;
        g_cur[i] = v;
    }
}
__global__ void k_scatter_edges(const int* __restrict__ src, const int* __restrict__ dst) {
    int e = blockIdx.x * blockDim.x + threadIdx.x;
    if (e < N_EDGES) {
        int pos = atomicAdd(&g_cur[dst[e]], 1);
        g_csrc[pos] = src[e];
    }
}

// ---------------- attention logits: el/er [N,H] ----------------
__global__ void k_attn_logits(const float* __restrict__ feat,
                              const float* __restrict__ al,
                              const float* __restrict__ ar, int F) {
    int warp = (blockIdx.x * blockDim.x + threadIdx.x) >> 5;
    int lane = threadIdx.x & 31;
    if (warp >= N_NODES * NH) return;
    int h = warp & 7;
    const float4* fp  = (const float4*)(feat + (size_t)warp * F);
    const float4* alp = (const float4*)(al + h * F);
    const float4* arp = (const float4*)(ar + h * F);
    float s1 = 0.f, s2 = 0.f;
    int nq = F >> 2;
    for (int q = lane; q < nq; q += 32) {
        float4 v = fp[q], x = alp[q], y = arp[q];
        s1 = fmaf(v.x, x.x, fmaf(v.y, x.y, fmaf(v.z, x.z, fmaf(v.w, x.w, s1))));
        s2 = fmaf(v.x, y.x, fmaf(v.y, y.y, fmaf(v.z, y.z, fmaf(v.w, y.w, s2))));
    }
#pragma unroll
    for (int o = 16; o; o >>= 1) {
        s1 += __shfl_xor_sync(0xffffffffu, s1, o);
        s2 += __shfl_xor_sync(0xffffffffu, s2, o);
    }
    if (lane == 0) { g_el[warp] = s1; g_er[warp] = s2; }
}

// ---------------- fused edge-softmax + aggregation ----------------
// One warp per (node, head). Pass 1: online softmax (coalesced csrc loads).
// Pass 2: per-edge broadcast loads with 1-deep prefetch of next src/el.
__global__ void k_aggregate_fused(const float* __restrict__ feat,
                                  const float* __restrict__ bias,
                                  float* __restrict__ out, int F) {
    int warp = (blockIdx.x * blockDim.x + threadIdx.x) >> 5;
    int lane = threadIdx.x & 31;
    if (warp >= N_NODES * NH) return;
    int n = warp >> 3, h = warp & 7;

    int start = g_rs[n];
    int deg   = g_cnt[n];
    float er_d = g_er[n * NH + h];

    // ---- pass 1: online softmax ----
    float m = -3.0e38f, ssum = 0.f;
    for (int i0 = 0; i0 < deg; i0 += 32) {
        int i = i0 + lane;
        float e = -3.0e38f;
        if (i < deg) {
            int s = g_csrc[start + i];
            float v = g_el[s * NH + h] + er_d;
            e = (v > 0.f) ? v : NEG_SLOPE * v;
        }
        float cm = e;
#pragma unroll
        for (int o = 16; o; o >>= 1) cm = fmaxf(cm, __shfl_xor_sync(0xffffffffu, cm, o));
        float nm = fmaxf(m, cm);
        float ex = (i < deg) ? __expf(e - nm) : 0.f;
#pragma unroll
        for (int o = 16; o; o >>= 1) ex += __shfl_xor_sync(0xffffffffu, ex, o);
        ssum = ssum * __expf(m - nm) + ex;
        m = nm;
    }
    float invs = (ssum > 0.f) ? (1.f / ssum) : 0.f;

    // ---- pass 2: weighted gather with 1-deep prefetch ----
    int nq = F >> 7;   // float4 groups per lane: 2 (F=256) or 4 (F=512)
    float4 acc4[4];
#pragma unroll
    for (int k = 0; k < 4; k++) acc4[k] = make_float4(0.f, 0.f, 0.f, 0.f);

    int   sCur  = (deg > 0) ? g_csrc[start] : 0;
    float elCur = (deg > 0) ? g_el[sCur * NH + h] : 0.f;
    for (int i = 0; i < deg; i++) {
        int   sNext  = (i + 1 < deg) ? g_csrc[start + i + 1] : 0;
        float elNext = (i + 1 < deg) ? g_el[sNext * NH + h] : 0.f;
        float v = elCur + er_d;
        v = (v > 0.f) ? v : NEG_SLOPE * v;
        float alpha = __expf(v - m) * invs;
        const float4* fp = (const float4*)(feat + ((size_t)sCur * NH + h) * F);
#pragma unroll 4
        for (int k = 0; k < nq; k++) {
            float4 t = fp[lane + 32 * k];
            acc4[k].x = fmaf(t.x, alpha, acc4[k].x);
            acc4[k].y = fmaf(t.y, alpha, acc4[k].y);
            acc4[k].z = fmaf(t.z, alpha, acc4[k].z);
            acc4[k].w = fmaf(t.w, alpha, acc4[k].w);
        }
        sCur = sNext; elCur = elNext;
    }

    float4* op = (float4*)(out + (size_t)warp * F);
    const float4* bp = (const float4*)(bias + h * F);
#pragma unroll 4
    for (int k = 0; k < nq; k++) {
        float4 bb = bp[lane + 32 * k];
        float4 r = acc4[k];
        r.x += bb.x; r.y += bb.y; r.z += bb.z; r.w += bb.w;
        op[lane + 32 * k] = r;
    }
}

// ---------------- GELU (exact) + head mean ----------------
__global__ void k_merge_heads(const float* __restrict__ agg, float* __restrict__ outh, int F) {
    int i = blockIdx.x * blockDim.x + threadIdx.x;
    if (i >= N_NODES * F) return;
    int n = i / F, f = i - n * F;
    float s = 0.f;
#pragma unroll
    for (int h = 0; h < NH; h++) {
        float x = agg[((size_t)n * NH + h) * F + f];
        s += 0.5f * x * (1.f + erff(x * 0.70710678f));
    }
    outh[i] = s * 0.125f;
}

// ---------------- host orchestration ----------------
extern "C" void kernel_launch(void* const* d_in, const int* in_sizes, int n_in,
                              void* d_out, int out_size) {
    const float* node = (const float*)d_in[0];
    const int*   src  = (const int*)d_in[1];
    const int*   dst  = (const int*)d_in[2];
    const float* W1   = (const float*)d_in[3];
    const float* al1  = (const float*)d_in[4];
    const float* ar1  = (const float*)d_in[5];
    const float* b1   = (const float*)d_in[6];
    const float* W2   = (const float*)d_in[7];
    const float* al2  = (const float*)d_in[8];
    const float* ar2  = (const float*)d_in[9];
    const float* b2   = (const float*)d_in[10];
    const float* W3   = (const float*)d_in[11];
    const float* al3  = (const float*)d_in[12];
    const float* ar3  = (const float*)d_in[13];
    const float* b3   = (const float*)d_in[14];
    float* out = (float*)d_out;

    float *feat, *agg, *hbuf, *wt;
    cudaGetSymbolAddress((void**)&feat, g_feat);
    cudaGetSymbolAddress((void**)&agg,  g_agg);
    cudaGetSymbolAddress((void**)&hbuf, g_h);
    cudaGetSymbolAddress((void**)&wt,   g_Wt);

    const int warps = N_NODES * NH;
    const int mtiles = (N_NODES + 127) / 128;

    // slots 1-3, then GEMM in slot 4 (ncu capture slot)
    k_zero_cnt<<<(N_NODES + 255) / 256, 256>>>();
    k_count<<<(N_EDGES + 255) / 256, 256>>>(dst);
    k_transpose<<<dim3((NH * F_HID) / 32, F_IN / 32), dim3(32, 8)>>>(W1, wt, F_IN, NH * F_HID);
    k_gemm_mma<<<dim3((NH * F_HID) / 128, mtiles), 256>>>(node, wt, feat, N_NODES, F_IN, NH * F_HID);

    // CSR finish
    int nb = (N_NODES + 511) / 512;
    k_scan_block<<<nb, 512>>>();
    k_scan_bsum<<<1, 1>>>(nb);
    k_scan_add<<<nb, 512>>>();
    k_scatter_edges<<<(N_EDGES + 255) / 256, 256>>>(src, dst);

    // layer 1 rest
    k_attn_logits<<<(warps * 32 + 255) / 256, 256>>>(feat, al1, ar1, F_HID);
    k_aggregate_fused<<<(warps * 32 + 255) / 256, 256>>>(feat, b1, agg, F_HID);
    k_merge_heads<<<(N_NODES * F_HID + 255) / 256, 256>>>(agg, hbuf, F_HID);

    // layer 2
    k_transpose<<<dim3((NH * F_HID) / 32, F_HID / 32), dim3(32, 8)>>>(W2, wt, F_HID, NH * F_HID);
    k_gemm_mma<<<dim3((NH * F_HID) / 128, mtiles), 256>>>(hbuf, wt, feat, N_NODES, F_HID, NH * F_HID);
    k_attn_logits<<<(warps * 32 + 255) / 256, 256>>>(feat, al2, ar2, F_HID);
    k_aggregate_fused<<<(warps * 32 + 255) / 256, 256>>>(feat, b2, agg, F_HID);
    k_merge_heads<<<(N_NODES * F_HID + 255) / 256, 256>>>(agg, hbuf, F_HID);

    // layer 3 (aggregate writes d_out directly)
    k_transpose<<<dim3((NH * F_OUT) / 32, F_HID / 32), dim3(32, 8)>>>(W3, wt, F_HID, NH * F_OUT);
    k_gemm_mma<<<dim3((NH * F_OUT) / 128, mtiles), 256>>>(hbuf, wt, feat, N_NODES, F_HID, NH * F_OUT);
    k_attn_logits<<<(warps * 32 + 255) / 256, 256>>>(feat, al3, ar3, F_OUT);
    k_aggregate_fused<<<(warps * 32 + 255) / 256, 256>>>(feat, b3, out, F_OUT);
}

// round 7
// speedup vs baseline: 1.0700x; 1.0700x over previous
#include <cuda_runtime.h>
#include <cuda_bf16.h>
#include <math.h>
#include <stdint.h>

#define N_NODES 20000
#define N_EDGES 160000
#define F_IN   512
#define F_HID  256
#define F_OUT  512
#define NH     8
#define NEG_SLOPE 0.2f

// ---------------- scratch (device globals; allocation-free) ----------------
__device__ float g_feat[(size_t)N_NODES * NH * F_OUT];
__device__ float g_agg [(size_t)N_NODES * NH * F_HID];
__device__ float g_h   [(size_t)N_NODES * F_HID];
__device__ __nv_bfloat16 g_Ahi[(size_t)N_NODES * F_IN];
__device__ __nv_bfloat16 g_Alo[(size_t)N_NODES * F_IN];
__device__ __nv_bfloat16 g_Bhi[1 << 20];
__device__ __nv_bfloat16 g_Blo[1 << 20];
__device__ float g_el  [N_NODES * NH];
__device__ float g_er  [N_NODES * NH];
__device__ int   g_cnt [N_NODES];
__device__ int   g_rs  [N_NODES];
__device__ int   g_cur [N_NODES];
__device__ int   g_csrc[N_EDGES];
__device__ int   g_bsum[64];

// =================== mma.sync bf16 split-3 GEMM ===================
// C[M,Nc] = A[M,K] @ W[K,Nc]. Inputs pre-split to bf16 hi/lo in global:
//   Ahi/Alo: [M,K] row-major;  Bhi/Blo: [Nc,K] (W^T) row-major.
// D += Ah*Bh + Ah*Bl + Al*Bh.
// Block tile 128x64, BK=32, 4 warps (warp tile 64x32), m16n8k16.

#define ROWB 80           // smem row stride in bytes (ldmatrix conflict-free)
#define SM_AHI 0
#define SM_ALO (128 * ROWB)
#define SM_BHI (2 * 128 * ROWB)
#define SM_BLO (2 * 128 * ROWB + 64 * ROWB)
#define SM_TOT (2 * 128 * ROWB + 2 * 64 * ROWB)   // 30720 B

__device__ __forceinline__ uint32_t smem_u32(const void* p) {
    uint32_t a;
    asm("{ .reg .u64 t; cvta.to.shared.u64 t, %1; cvt.u32.u64 %0, t; }" : "=r"(a) : "l"(p));
    return a;
}
__device__ __forceinline__ void ldm_x4(uint32_t* r, uint32_t addr) {
    asm volatile("ldmatrix.sync.aligned.m8n8.x4.shared.b16 {%0,%1,%2,%3}, [%4];"
                 : "=r"(r[0]), "=r"(r[1]), "=r"(r[2]), "=r"(r[3]) : "r"(addr));
}
__device__ __forceinline__ void ldm_x2(uint32_t* r, uint32_t addr) {
    asm volatile("ldmatrix.sync.aligned.m8n8.x2.shared.b16 {%0,%1}, [%2];"
                 : "=r"(r[0]), "=r"(r[1]) : "r"(addr));
}
__device__ __forceinline__ void mma_bf16(float* d, const uint32_t* a, const uint32_t* b) {
    asm volatile(
        "mma.sync.aligned.m16n8k16.row.col.f32.bf16.bf16.f32 "
        "{%0,%1,%2,%3}, {%4,%5,%6,%7}, {%8,%9}, {%0,%1,%2,%3};"
        : "+f"(d[0]), "+f"(d[1]), "+f"(d[2]), "+f"(d[3])
        : "r"(a[0]), "r"(a[1]), "r"(a[2]), "r"(a[3]), "r"(b[0]), "r"(b[1]));
}

__global__ void __launch_bounds__(128) k_gemm_mma(const __nv_bfloat16* __restrict__ Ahi,
                                                  const __nv_bfloat16* __restrict__ Alo,
                                                  const __nv_bfloat16* __restrict__ Bhi,
                                                  const __nv_bfloat16* __restrict__ Blo,
                                                  float* __restrict__ C,
                                                  int M, int K, int Nc) {
    __shared__ __align__(16) char sm[SM_TOT];
    const uint32_t smb = smem_u32(sm);

    const int tid  = threadIdx.x;
    const int wid  = tid >> 5;
    const int lane = tid & 31;
    const int m0 = blockIdx.y * 128;
    const int n0 = blockIdx.x * 64;
    const int wm = (wid >> 1) * 64;
    const int wn = (wid & 1) * 32;

    float acc[4][4][4] = {};
    const uint4 z4 = make_uint4(0u, 0u, 0u, 0u);

    const uint32_t aRow = wm + (lane & 15);
    const uint32_t aKof = (lane >> 4) * 16;
    const uint32_t bRow = wn + (lane & 7);
    const uint32_t bKof = ((lane >> 3) & 1) * 16;
    const uint32_t aHiAddr = smb + SM_AHI + aRow * ROWB + aKof;
    const uint32_t aLoAddr = smb + SM_ALO + aRow * ROWB + aKof;
    const uint32_t bHiAddr = smb + SM_BHI + bRow * ROWB + bKof;
    const uint32_t bLoAddr = smb + SM_BLO + bRow * ROWB + bKof;

    for (int k0 = 0; k0 < K; k0 += 32) {
        if (k0) __syncthreads();
        // ---- A: 128x32 bf16, hi+lo (uint4 = 8 bf16 per load) ----
#pragma unroll
        for (int it = 0; it < 4; it++) {
            int idx = tid + (it << 7);            // 0..511
            int r  = idx >> 2;
            int c8 = (idx & 3) << 3;              // 0,8,16,24
            size_t go = (size_t)(m0 + r) * K + k0 + c8;
            uint4 hv = (m0 + r < M) ? *(const uint4*)&Ahi[go] : z4;
            uint4 lv = (m0 + r < M) ? *(const uint4*)&Alo[go] : z4;
            *(uint4*)(sm + SM_AHI + r * ROWB + c8 * 2) = hv;
            *(uint4*)(sm + SM_ALO + r * ROWB + c8 * 2) = lv;
        }
        // ---- B: 64x32 bf16, hi+lo ----
#pragma unroll
        for (int it = 0; it < 2; it++) {
            int idx = tid + (it << 7);            // 0..255
            int r  = idx >> 2;
            int c8 = (idx & 3) << 3;
            size_t go = (size_t)(n0 + r) * K + k0 + c8;
            uint4 hv = *(const uint4*)&Bhi[go];
            uint4 lv = *(const uint4*)&Blo[go];
            *(uint4*)(sm + SM_BHI + r * ROWB + c8 * 2) = hv;
            *(uint4*)(sm + SM_BLO + r * ROWB + c8 * 2) = lv;
        }
        __syncthreads();

        // ---- compute: 2 k-steps of m16n8k16 ----
#pragma unroll
        for (int ks = 0; ks < 2; ks++) {
            uint32_t ahi[4][4], alo[4][4], bhi[4][2], blo[4][2];
#pragma unroll
            for (int mf = 0; mf < 4; mf++) {
                ldm_x4(ahi[mf], aHiAddr + mf * (16 * ROWB) + ks * 32);
                ldm_x4(alo[mf], aLoAddr + mf * (16 * ROWB) + ks * 32);
            }
#pragma unroll
            for (int nf = 0; nf < 4; nf++) {
                ldm_x2(bhi[nf], bHiAddr + nf * (8 * ROWB) + ks * 32);
                ldm_x2(blo[nf], bLoAddr + nf * (8 * ROWB) + ks * 32);
            }
#pragma unroll
            for (int mf = 0; mf < 4; mf++)
#pragma unroll
                for (int nf = 0; nf < 4; nf++) {
                    mma_bf16(acc[mf][nf], ahi[mf], bhi[nf]);
                    mma_bf16(acc[mf][nf], ahi[mf], blo[nf]);
                    mma_bf16(acc[mf][nf], alo[mf], bhi[nf]);
                }
        }
    }

    // ---- epilogue ----
#pragma unroll
    for (int mf = 0; mf < 4; mf++) {
        int row0 = m0 + wm + mf * 16 + (lane >> 2);
#pragma unroll
        for (int nf = 0; nf < 4; nf++) {
            int col = n0 + wn + nf * 8 + (lane & 3) * 2;
            if (row0 < M)
                *(float2*)&C[(size_t)row0 * Nc + col] = make_float2(acc[mf][nf][0], acc[mf][nf][1]);
            if (row0 + 8 < M)
                *(float2*)&C[(size_t)(row0 + 8) * Nc + col] = make_float2(acc[mf][nf][2], acc[mf][nf][3]);
        }
    }
}

// ---------------- fp32 -> bf16 hi/lo split ----------------
__global__ void k_split(const float* __restrict__ x,
                        __nv_bfloat16* __restrict__ hi,
                        __nv_bfloat16* __restrict__ lo, int n4) {
    int i = blockIdx.x * blockDim.x + threadIdx.x;
    if (i >= n4) return;
    float4 v = ((const float4*)x)[i];
    __nv_bfloat16 hx = __float2bfloat16_rn(v.x);
    __nv_bfloat16 hy = __float2bfloat16_rn(v.y);
    __nv_bfloat16 hz = __float2bfloat16_rn(v.z);
    __nv_bfloat16 hw = __float2bfloat16_rn(v.w);
    __nv_bfloat16 lx = __float2bfloat16_rn(v.x - __bfloat162float(hx));
    __nv_bfloat16 ly = __float2bfloat16_rn(v.y - __bfloat162float(hy));
    __nv_bfloat16 lz = __float2bfloat16_rn(v.z - __bfloat162float(hz));
    __nv_bfloat16 lw = __float2bfloat16_rn(v.w - __bfloat162float(hw));
    __nv_bfloat162 h0 = __nv_bfloat162(hx, hy), h1 = __nv_bfloat162(hz, hw);
    __nv_bfloat162 l0 = __nv_bfloat162(lx, ly), l1 = __nv_bfloat162(lz, lw);
    *(uint2*)&hi[4 * (size_t)i] = make_uint2(*(uint32_t*)&h0, *(uint32_t*)&h1);
    *(uint2*)&lo[4 * (size_t)i] = make_uint2(*(uint32_t*)&l0, *(uint32_t*)&l1);
}

// ---------------- W transpose + split: Bhi/Blo[n][k] = split(W[k][n]) ----------------
__global__ void k_transpose_split(const float* __restrict__ W,
                                  __nv_bfloat16* __restrict__ hi,
                                  __nv_bfloat16* __restrict__ lo,
                                  int K, int Nc) {
    __shared__ float tile[32][33];
    int n0 = blockIdx.x * 32, k0 = blockIdx.y * 32;
    int tx = threadIdx.x, ty = threadIdx.y;
#pragma unroll
    for (int j = 0; j < 32; j += 8)
        tile[ty + j][tx] = W[(size_t)(k0 + ty + j) * Nc + n0 + tx];
    __syncthreads();
#pragma unroll
    for (int j = 0; j < 32; j += 8) {
        float v = tile[tx][ty + j];
        __nv_bfloat16 h = __float2bfloat16_rn(v);
        __nv_bfloat16 l = __float2bfloat16_rn(v - __bfloat162float(h));
        size_t o = (size_t)(n0 + ty + j) * K + k0 + tx;
        hi[o] = h;
        lo[o] = l;
    }
}

// ---------------- CSR build ----------------
__global__ void k_zero_cnt() {
    int i = blockIdx.x * blockDim.x + threadIdx.x;
    if (i < N_NODES) g_cnt[i] = 0;
}
__global__ void k_count(const int* __restrict__ dst) {
    int e = blockIdx.x * blockDim.x + threadIdx.x;
    if (e < N_EDGES) atomicAdd(&g_cnt[dst[e]], 1);
}
__global__ void k_scan_block() {
    __shared__ int s[512];
    int i = blockIdx.x * 512 + threadIdx.x;
    int v = (i < N_NODES) ? g_cnt[i] : 0;
    s[threadIdx.x] = v;
    __syncthreads();
    for (int off = 1; off < 512; off <<= 1) {
        int t = (threadIdx.x >= off) ? s[threadIdx.x - off] : 0;
        __syncthreads();
        s[threadIdx.x] += t;
        __syncthreads();
    }
    if (i < N_NODES) g_rs[i] = s[threadIdx.x] - v;
    if (threadIdx.x == 511) g_bsum[blockIdx.x] = s[511];
}
__global__ void k_scan_bsum(int nb) {
    if (threadIdx.x == 0 && blockIdx.x == 0) {
        int acc = 0;
        for (int i = 0; i < nb; i++) { int t = g_bsum[i]; g_bsum[i] = acc; acc += t; }
    }
}
__global__ void k_scan_add() {
    int i = blockIdx.x * 512 + threadIdx.x;
    if (i < N_NODES) {
        int v = g_rs[i] + g_bsum[blockIdx.x];
        g_rs[i]  = v;
        g_cur[i] = v;
    }
}
__global__ void k_scatter_edges(const int* __restrict__ src, const int* __restrict__ dst) {
    int e = blockIdx.x * blockDim.x + threadIdx.x;
    if (e < N_EDGES) {
        int pos = atomicAdd(&g_cur[dst[e]], 1);
        g_csrc[pos] = src[e];
    }
}

// ---------------- attention logits: el/er [N,H] ----------------
__global__ void k_attn_logits(const float* __restrict__ feat,
                              const float* __restrict__ al,
                              const float* __restrict__ ar, int F) {
    int warp = (blockIdx.x * blockDim.x + threadIdx.x) >> 5;
    int lane = threadIdx.x & 31;
    if (warp >= N_NODES * NH) return;
    int h = warp & 7;
    const float4* fp  = (const float4*)(feat + (size_t)warp * F);
    const float4* alp = (const float4*)(al + h * F);
    const float4* arp = (const float4*)(ar + h * F);
    float s1 = 0.f, s2 = 0.f;
    int nq = F >> 2;
    for (int q = lane; q < nq; q += 32) {
        float4 v = fp[q], x = alp[q], y = arp[q];
        s1 = fmaf(v.x, x.x, fmaf(v.y, x.y, fmaf(v.z, x.z, fmaf(v.w, x.w, s1))));
        s2 = fmaf(v.x, y.x, fmaf(v.y, y.y, fmaf(v.z, y.z, fmaf(v.w, y.w, s2))));
    }
#pragma unroll
    for (int o = 16; o; o >>= 1) {
        s1 += __shfl_xor_sync(0xffffffffu, s1, o);
        s2 += __shfl_xor_sync(0xffffffffu, s2, o);
    }
    if (lane == 0) { g_el[warp] = s1; g_er[warp] = s2; }
}

// ---------------- fused edge-softmax + aggregation ----------------
__global__ void k_aggregate_fused(const float* __restrict__ feat,
                                  const float* __restrict__ bias,
                                  float* __restrict__ out, int F) {
    int warp = (blockIdx.x * blockDim.x + threadIdx.x) >> 5;
    int lane = threadIdx.x & 31;
    if (warp >= N_NODES * NH) return;
    int n = warp >> 3, h = warp & 7;

    int start = g_rs[n];
    int deg   = g_cnt[n];
    float er_d = g_er[n * NH + h];

    // ---- pass 1: online softmax ----
    float m = -3.0e38f, ssum = 0.f;
    for (int i0 = 0; i0 < deg; i0 += 32) {
        int i = i0 + lane;
        float e = -3.0e38f;
        if (i < deg) {
            int s = g_csrc[start + i];
            float v = g_el[s * NH + h] + er_d;
            e = (v > 0.f) ? v : NEG_SLOPE * v;
        }
        float cm = e;
#pragma unroll
        for (int o = 16; o; o >>= 1) cm = fmaxf(cm, __shfl_xor_sync(0xffffffffu, cm, o));
        float nm = fmaxf(m, cm);
        float ex = (i < deg) ? __expf(e - nm) : 0.f;
#pragma unroll
        for (int o = 16; o; o >>= 1) ex += __shfl_xor_sync(0xffffffffu, ex, o);
        ssum = ssum * __expf(m - nm) + ex;
        m = nm;
    }
    float invs = (ssum > 0.f) ? (1.f / ssum) : 0.f;

    // ---- pass 2: weighted gather with 1-deep prefetch ----
    int nq = F >> 7;
    float4 acc4[4];
#pragma unroll
    for (int k = 0; k < 4; k++) acc4[k] = make_float4(0.f, 0.f, 0.f, 0.f);

    int   sCur  = (deg > 0) ? g_csrc[start] : 0;
    float elCur = (deg > 0) ? g_el[sCur * NH + h] : 0.f;
    for (int i = 0; i < deg; i++) {
        int   sNext  = (i + 1 < deg) ? g_csrc[start + i + 1] : 0;
        float elNext = (i + 1 < deg) ? g_el[sNext * NH + h] : 0.f;
        float v = elCur + er_d;
        v = (v > 0.f) ? v : NEG_SLOPE * v;
        float alpha = __expf(v - m) * invs;
        const float4* fp = (const float4*)(feat + ((size_t)sCur * NH + h) * F);
#pragma unroll 4
        for (int k = 0; k < nq; k++) {
            float4 t = fp[lane + 32 * k];
            acc4[k].x = fmaf(t.x, alpha, acc4[k].x);
            acc4[k].y = fmaf(t.y, alpha, acc4[k].y);
            acc4[k].z = fmaf(t.z, alpha, acc4[k].z);
            acc4[k].w = fmaf(t.w, alpha, acc4[k].w);
        }
        sCur = sNext; elCur = elNext;
    }

    float4* op = (float4*)(out + (size_t)warp * F);
    const float4* bp = (const float4*)(bias + h * F);
#pragma unroll 4
    for (int k = 0; k < nq; k++) {
        float4 bb = bp[lane + 32 * k];
        float4 r = acc4[k];
        r.x += bb.x; r.y += bb.y; r.z += bb.z; r.w += bb.w;
        op[lane + 32 * k] = r;
    }
}

// ---------------- GELU (exact) + head mean ----------------
__global__ void k_merge_heads(const float* __restrict__ agg, float* __restrict__ outh, int F) {
    int i = blockIdx.x * blockDim.x + threadIdx.x;
    if (i >= N_NODES * F) return;
    int n = i / F, f = i - n * F;
    float s = 0.f;
#pragma unroll
    for (int h = 0; h < NH; h++) {
        float x = agg[((size_t)n * NH + h) * F + f];
        s += 0.5f * x * (1.f + erff(x * 0.70710678f));
    }
    outh[i] = s * 0.125f;
}

// ---------------- host orchestration ----------------
extern "C" void kernel_launch(void* const* d_in, const int* in_sizes, int n_in,
                              void* d_out, int out_size) {
    const float* node = (const float*)d_in[0];
    const int*   src  = (const int*)d_in[1];
    const int*   dst  = (const int*)d_in[2];
    const float* W1   = (const float*)d_in[3];
    const float* al1  = (const float*)d_in[4];
    const float* ar1  = (const float*)d_in[5];
    const float* b1   = (const float*)d_in[6];
    const float* W2   = (const float*)d_in[7];
    const float* al2  = (const float*)d_in[8];
    const float* ar2  = (const float*)d_in[9];
    const float* b2   = (const float*)d_in[10];
    const float* W3   = (const float*)d_in[11];
    const float* al3  = (const float*)d_in[12];
    const float* ar3  = (const float*)d_in[13];
    const float* b3   = (const float*)d_in[14];
    float* out = (float*)d_out;

    float *feat, *agg, *hbuf;
    __nv_bfloat16 *ahi, *alo, *bhi, *blo;
    cudaGetSymbolAddress((void**)&feat, g_feat);
    cudaGetSymbolAddress((void**)&agg,  g_agg);
    cudaGetSymbolAddress((void**)&hbuf, g_h);
    cudaGetSymbolAddress((void**)&ahi,  g_Ahi);
    cudaGetSymbolAddress((void**)&alo,  g_Alo);
    cudaGetSymbolAddress((void**)&bhi,  g_Bhi);
    cudaGetSymbolAddress((void**)&blo,  g_Blo);

    const int warps = N_NODES * NH;
    const int mtiles = (N_NODES + 127) / 128;

    // slots 1-3, GEMM in slot 4 (ncu capture slot)
    k_zero_cnt<<<(N_NODES + 255) / 256, 256>>>();
    k_split<<<(N_NODES * F_IN / 4 + 255) / 256, 256>>>(node, ahi, alo, N_NODES * F_IN / 4);
    k_transpose_split<<<dim3((NH * F_HID) / 32, F_IN / 32), dim3(32, 8)>>>(W1, bhi, blo, F_IN, NH * F_HID);
    k_gemm_mma<<<dim3((NH * F_HID) / 64, mtiles), 128>>>(ahi, alo, bhi, blo, feat, N_NODES, F_IN, NH * F_HID);

    // CSR build
    k_count<<<(N_EDGES + 255) / 256, 256>>>(dst);
    int nb = (N_NODES + 511) / 512;
    k_scan_block<<<nb, 512>>>();
    k_scan_bsum<<<1, 1>>>(nb);
    k_scan_add<<<nb, 512>>>();
    k_scatter_edges<<<(N_EDGES + 255) / 256, 256>>>(src, dst);

    // layer 1 rest
    k_attn_logits<<<(warps * 32 + 255) / 256, 256>>>(feat, al1, ar1, F_HID);
    k_aggregate_fused<<<(warps * 32 + 255) / 256, 256>>>(feat, b1, agg, F_HID);
    k_merge_heads<<<(N_NODES * F_HID + 255) / 256, 256>>>(agg, hbuf, F_HID);

    // layer 2
    k_split<<<(N_NODES * F_HID / 4 + 255) / 256, 256>>>(hbuf, ahi, alo, N_NODES * F_HID / 4);
    k_transpose_split<<<dim3((NH * F_HID) / 32, F_HID / 32), dim3(32, 8)>>>(W2, bhi, blo, F_HID, NH * F_HID);
    k_gemm_mma<<<dim3((NH * F_HID) / 64, mtiles), 128>>>(ahi, alo, bhi, blo, feat, N_NODES, F_HID, NH * F_HID);
    k_attn_logits<<<(warps * 32 + 255) / 256, 256>>>(feat, al2, ar2, F_HID);
    k_aggregate_fused<<<(warps * 32 + 255) / 256, 256>>>(feat, b2, agg, F_HID);
    k_merge_heads<<<(N_NODES * F_HID + 255) / 256, 256>>>(agg, hbuf, F_HID);

    // layer 3 (aggregate writes d_out directly)
    k_split<<<(N_NODES * F_HID / 4 + 255) / 256, 256>>>(hbuf, ahi, alo, N_NODES * F_HID / 4);
    k_transpose_split<<<dim3((NH * F_OUT) / 32, F_HID / 32), dim3(32, 8)>>>(W3, bhi, blo, F_HID, NH * F_OUT);
    k_gemm_mma<<<dim3((NH * F_OUT) / 64, mtiles), 128>>>(ahi, alo, bhi, blo, feat, N_NODES, F_HID, NH * F_OUT);
    k_attn_logits<<<(warps * 32 + 255) / 256, 256>>>(feat, al3, ar3, F_OUT);
    k_aggregate_fused<<<(warps * 32 + 255) / 256, 256>>>(feat, b3, out, F_OUT);
}

// round 8
// speedup vs baseline: 1.0708x; 1.0007x over previous
#include <cuda_runtime.h>
#include <cuda_bf16.h>
#include <math.h>
#include <stdint.h>

#define N_NODES 20000
#define N_EDGES 160000
#define F_IN   512
#define F_HID  256
#define F_OUT  512
#define NH     8
#define NEG_SLOPE 0.2f

// ---------------- scratch (device globals; allocation-free) ----------------
__device__ float g_feat[(size_t)N_NODES * NH * F_OUT];
__device__ float g_agg [(size_t)N_NODES * NH * F_HID];
__device__ float g_h   [(size_t)N_NODES * F_HID];
__device__ __nv_bfloat16 g_Ahi[(size_t)N_NODES * F_IN];
__device__ __nv_bfloat16 g_Alo[(size_t)N_NODES * F_IN];
__device__ __nv_bfloat16 g_Bhi[1 << 20];
__device__ __nv_bfloat16 g_Blo[1 << 20];
__device__ float g_el  [N_NODES * NH];
__device__ float g_er  [N_NODES * NH];
__device__ int   g_cnt [N_NODES];
__device__ int   g_rs  [N_NODES];
__device__ int   g_cur [N_NODES];
__device__ int   g_csrc[N_EDGES];
__device__ int   g_bsum[64];

// =================== mma.sync bf16 split-3 GEMM ===================
// C[M,Nc] = A[M,K] @ W[K,Nc]. Inputs pre-split to bf16 hi/lo in global:
//   Ahi/Alo: [M,K] row-major;  Bhi/Blo: [Nc,K] (W^T) row-major.
// D += Ah*Bh + Ah*Bl + Al*Bh.
// Block tile 128x64, BK=32, 4 warps (warp tile 64x32), m16n8k16.

#define ROWB 80           // smem row stride in bytes (ldmatrix conflict-free)
#define SM_AHI 0
#define SM_ALO (128 * ROWB)
#define SM_BHI (2 * 128 * ROWB)
#define SM_BLO (2 * 128 * ROWB + 64 * ROWB)
#define SM_TOT (2 * 128 * ROWB + 2 * 64 * ROWB)   // 30720 B

__device__ __forceinline__ uint32_t smem_u32(const void* p) {
    uint32_t a;
    asm("{ .reg .u64 t; cvta.to.shared.u64 t, %1; cvt.u32.u64 %0, t; }" : "=r"(a) : "l"(p));
    return a;
}
__device__ __forceinline__ void ldm_x4(uint32_t* r, uint32_t addr) {
    asm volatile("ldmatrix.sync.aligned.m8n8.x4.shared.b16 {%0,%1,%2,%3}, [%4];"
                 : "=r"(r[0]), "=r"(r[1]), "=r"(r[2]), "=r"(r[3]) : "r"(addr));
}
__device__ __forceinline__ void ldm_x2(uint32_t* r, uint32_t addr) {
    asm volatile("ldmatrix.sync.aligned.m8n8.x2.shared.b16 {%0,%1}, [%2];"
                 : "=r"(r[0]), "=r"(r[1]) : "r"(addr));
}
__device__ __forceinline__ void mma_bf16(float* d, const uint32_t* a, const uint32_t* b) {
    asm volatile(
        "mma.sync.aligned.m16n8k16.row.col.f32.bf16.bf16.f32 "
        "{%0,%1,%2,%3}, {%4,%5,%6,%7}, {%8,%9}, {%0,%1,%2,%3};"
        : "+f"(d[0]), "+f"(d[1]), "+f"(d[2]), "+f"(d[3])
        : "r"(a[0]), "r"(a[1]), "r"(a[2]), "r"(a[3]), "r"(b[0]), "r"(b[1]));
}

__global__ void __launch_bounds__(128) k_gemm_mma(const __nv_bfloat16* __restrict__ Ahi,
                                                  const __nv_bfloat16* __restrict__ Alo,
                                                  const __nv_bfloat16* __restrict__ Bhi,
                                                  const __nv_bfloat16* __restrict__ Blo,
                                                  float* __restrict__ C,
                                                  int M, int K, int Nc) {
    __shared__ __align__(16) char sm[SM_TOT];
    const uint32_t smb = smem_u32(sm);

    const int tid  = threadIdx.x;
    const int wid  = tid >> 5;
    const int lane = tid & 31;
    const int m0 = blockIdx.y * 128;
    const int n0 = blockIdx.x * 64;
    const int wm = (wid >> 1) * 64;
    const int wn = (wid & 1) * 32;

    float acc[4][4][4] = {};
    const uint4 z4 = make_uint4(0u, 0u, 0u, 0u);

    const uint32_t aRow = wm + (lane & 15);
    const uint32_t aKof = (lane >> 4) * 16;
    const uint32_t bRow = wn + (lane & 7);
    const uint32_t bKof = ((lane >> 3) & 1) * 16;
    const uint32_t aHiAddr = smb + SM_AHI + aRow * ROWB + aKof;
    const uint32_t aLoAddr = smb + SM_ALO + aRow * ROWB + aKof;
    const uint32_t bHiAddr = smb + SM_BHI + bRow * ROWB + bKof;
    const uint32_t bLoAddr = smb + SM_BLO + bRow * ROWB + bKof;

    for (int k0 = 0; k0 < K; k0 += 32) {
        if (k0) __syncthreads();
        // ---- A: 128x32 bf16, hi+lo (uint4 = 8 bf16 per load) ----
#pragma unroll
        for (int it = 0; it < 4; it++) {
            int idx = tid + (it << 7);            // 0..511
            int r  = idx >> 2;
            int c8 = (idx & 3) << 3;              // 0,8,16,24
            size_t go = (size_t)(m0 + r) * K + k0 + c8;
            uint4 hv = (m0 + r < M) ? *(const uint4*)&Ahi[go] : z4;
            uint4 lv = (m0 + r < M) ? *(const uint4*)&Alo[go] : z4;
            *(uint4*)(sm + SM_AHI + r * ROWB + c8 * 2) = hv;
            *(uint4*)(sm + SM_ALO + r * ROWB + c8 * 2) = lv;
        }
        // ---- B: 64x32 bf16, hi+lo ----
#pragma unroll
        for (int it = 0; it < 2; it++) {
            int idx = tid + (it << 7);            // 0..255
            int r  = idx >> 2;
            int c8 = (idx & 3) << 3;
            size_t go = (size_t)(n0 + r) * K + k0 + c8;
            uint4 hv = *(const uint4*)&Bhi[go];
            uint4 lv = *(const uint4*)&Blo[go];
            *(uint4*)(sm + SM_BHI + r * ROWB + c8 * 2) = hv;
            *(uint4*)(sm + SM_BLO + r * ROWB + c8 * 2) = lv;
        }
        __syncthreads();

        // ---- compute: 2 k-steps of m16n8k16 ----
#pragma unroll
        for (int ks = 0; ks < 2; ks++) {
            uint32_t ahi[4][4], alo[4][4], bhi[4][2], blo[4][2];
#pragma unroll
            for (int mf = 0; mf < 4; mf++) {
                ldm_x4(ahi[mf], aHiAddr + mf * (16 * ROWB) + ks * 32);
                ldm_x4(alo[mf], aLoAddr + mf * (16 * ROWB) + ks * 32);
            }
#pragma unroll
            for (int nf = 0; nf < 4; nf++) {
                ldm_x2(bhi[nf], bHiAddr + nf * (8 * ROWB) + ks * 32);
                ldm_x2(blo[nf], bLoAddr + nf * (8 * ROWB) + ks * 32);
            }
#pragma unroll
            for (int mf = 0; mf < 4; mf++)
#pragma unroll
                for (int nf = 0; nf < 4; nf++) {
                    mma_bf16(acc[mf][nf], ahi[mf], bhi[nf]);
                    mma_bf16(acc[mf][nf], ahi[mf], blo[nf]);
                    mma_bf16(acc[mf][nf], alo[mf], bhi[nf]);
                }
        }
    }

    // ---- epilogue ----
#pragma unroll
    for (int mf = 0; mf < 4; mf++) {
        int row0 = m0 + wm + mf * 16 + (lane >> 2);
#pragma unroll
        for (int nf = 0; nf < 4; nf++) {
            int col = n0 + wn + nf * 8 + (lane & 3) * 2;
            if (row0 < M)
                *(float2*)&C[(size_t)row0 * Nc + col] = make_float2(acc[mf][nf][0], acc[mf][nf][1]);
            if (row0 + 8 < M)
                *(float2*)&C[(size_t)(row0 + 8) * Nc + col] = make_float2(acc[mf][nf][2], acc[mf][nf][3]);
        }
    }
}

// ---------------- fp32 -> bf16 hi/lo split ----------------
__global__ void k_split(const float* __restrict__ x,
                        __nv_bfloat16* __restrict__ hi,
                        __nv_bfloat16* __restrict__ lo, int n4) {
    int i = blockIdx.x * blockDim.x + threadIdx.x;
    if (i >= n4) return;
    float4 v = ((const float4*)x)[i];
    __nv_bfloat16 hx = __float2bfloat16_rn(v.x);
    __nv_bfloat16 hy = __float2bfloat16_rn(v.y);
    __nv_bfloat16 hz = __float2bfloat16_rn(v.z);
    __nv_bfloat16 hw = __float2bfloat16_rn(v.w);
    __nv_bfloat16 lx = __float2bfloat16_rn(v.x - __bfloat162float(hx));
    __nv_bfloat16 ly = __float2bfloat16_rn(v.y - __bfloat162float(hy));
    __nv_bfloat16 lz = __float2bfloat16_rn(v.z - __bfloat162float(hz));
    __nv_bfloat16 lw = __float2bfloat16_rn(v.w - __bfloat162float(hw));
    __nv_bfloat162 h0 = __nv_bfloat162(hx, hy), h1 = __nv_bfloat162(hz, hw);
    __nv_bfloat162 l0 = __nv_bfloat162(lx, ly), l1 = __nv_bfloat162(lz, lw);
    *(uint2*)&hi[4 * (size_t)i] = make_uint2(*(uint32_t*)&h0, *(uint32_t*)&h1);
    *(uint2*)&lo[4 * (size_t)i] = make_uint2(*(uint32_t*)&l0, *(uint32_t*)&l1);
}

// ---------------- W transpose + split: Bhi/Blo[n][k] = split(W[k][n]) ----------------
__global__ void k_transpose_split(const float* __restrict__ W,
                                  __nv_bfloat16* __restrict__ hi,
                                  __nv_bfloat16* __restrict__ lo,
                                  int K, int Nc) {
    __shared__ float tile[32][33];
    int n0 = blockIdx.x * 32, k0 = blockIdx.y * 32;
    int tx = threadIdx.x, ty = threadIdx.y;
#pragma unroll
    for (int j = 0; j < 32; j += 8)
        tile[ty + j][tx] = W[(size_t)(k0 + ty + j) * Nc + n0 + tx];
    __syncthreads();
#pragma unroll
    for (int j = 0; j < 32; j += 8) {
        float v = tile[tx][ty + j];
        __nv_bfloat16 h = __float2bfloat16_rn(v);
        __nv_bfloat16 l = __float2bfloat16_rn(v - __bfloat162float(h));
        size_t o = (size_t)(n0 + ty + j) * K + k0 + tx;
        hi[o] = h;
        lo[o] = l;
    }
}

// ---------------- CSR build ----------------
__global__ void k_zero_cnt() {
    int i = blockIdx.x * blockDim.x + threadIdx.x;
    if (i < N_NODES) g_cnt[i] = 0;
}
__global__ void k_count(const int* __restrict__ dst) {
    int e = blockIdx.x * blockDim.x + threadIdx.x;
    if (e < N_EDGES) atomicAdd(&g_cnt[dst[e]], 1);
}
__global__ void k_scan_block() {
    __shared__ int s[512];
    int i = blockIdx.x * 512 + threadIdx.x;
    int v = (i < N_NODES) ? g_cnt[i] : 0;
    s[threadIdx.x] = v;
    __syncthreads();
    for (int off = 1; off < 512; off <<= 1) {
        int t = (threadIdx.x >= off) ? s[threadIdx.x - off] : 0;
        __syncthreads();
        s[threadIdx.x] += t;
        __syncthreads();
    }
    if (i < N_NODES) g_rs[i] = s[threadIdx.x] - v;
    if (threadIdx.x == 511) g_bsum[blockIdx.x] = s[511];
}
__global__ void k_scan_bsum(int nb) {
    if (threadIdx.x == 0 && blockIdx.x == 0) {
        int acc = 0;
        for (int i = 0; i < nb; i++) { int t = g_bsum[i]; g_bsum[i] = acc; acc += t; }
    }
}
__global__ void k_scan_add() {
    int i = blockIdx.x * 512 + threadIdx.x;
    if (i < N_NODES) {
        int v = g_rs[i] + g_bsum[blockIdx.x];
        g_rs[i]  = v;
        g_cur[i] = v;
    }
}
__global__ void k_scatter_edges(const int* __restrict__ src, const int* __restrict__ dst) {
    int e = blockIdx.x * blockDim.x + threadIdx.x;
    if (e < N_EDGES) {
        int pos = atomicAdd(&g_cur[dst[e]], 1);
        g_csrc[pos] = src[e];
    }
}

// ---------------- attention logits: el/er [N,H] ----------------
__global__ void k_attn_logits(const float* __restrict__ feat,
                              const float* __restrict__ al,
                              const float* __restrict__ ar, int F) {
    int warp = (blockIdx.x * blockDim.x + threadIdx.x) >> 5;
    int lane = threadIdx.x & 31;
    if (warp >= N_NODES * NH) return;
    int h = warp & 7;
    const float4* fp  = (const float4*)(feat + (size_t)warp * F);
    const float4* alp = (const float4*)(al + h * F);
    const float4* arp = (const float4*)(ar + h * F);
    float s1 = 0.f, s2 = 0.f;
    int nq = F >> 2;
    for (int q = lane; q < nq; q += 32) {
        float4 v = fp[q], x = alp[q], y = arp[q];
        s1 = fmaf(v.x, x.x, fmaf(v.y, x.y, fmaf(v.z, x.z, fmaf(v.w, x.w, s1))));
        s2 = fmaf(v.x, y.x, fmaf(v.y, y.y, fmaf(v.z, y.z, fmaf(v.w, y.w, s2))));
    }
#pragma unroll
    for (int o = 16; o; o >>= 1) {
        s1 += __shfl_xor_sync(0xffffffffu, s1, o);
        s2 += __shfl_xor_sync(0xffffffffu, s2, o);
    }
    if (lane == 0) { g_el[warp] = s1; g_er[warp] = s2; }
}

// ---------------- fused edge-softmax + aggregation ----------------
__global__ void k_aggregate_fused(const float* __restrict__ feat,
                                  const float* __restrict__ bias,
                                  float* __restrict__ out, int F) {
    int warp = (blockIdx.x * blockDim.x + threadIdx.x) >> 5;
    int lane = threadIdx.x & 31;
    if (warp >= N_NODES * NH) return;
    int n = warp >> 3, h = warp & 7;

    int start = g_rs[n];
    int deg   = g_cnt[n];
    float er_d = g_er[n * NH + h];

    // ---- pass 1: online softmax ----
    float m = -3.0e38f, ssum = 0.f;
    for (int i0 = 0; i0 < deg; i0 += 32) {
        int i = i0 + lane;
        float e = -3.0e38f;
        if (i < deg) {
            int s = g_csrc[start + i];
            float v = g_el[s * NH + h] + er_d;
            e = (v > 0.f) ? v : NEG_SLOPE * v;
        }
        float cm = e;
#pragma unroll
        for (int o = 16; o; o >>= 1) cm = fmaxf(cm, __shfl_xor_sync(0xffffffffu, cm, o));
        float nm = fmaxf(m, cm);
        float ex = (i < deg) ? __expf(e - nm) : 0.f;
#pragma unroll
        for (int o = 16; o; o >>= 1) ex += __shfl_xor_sync(0xffffffffu, ex, o);
        ssum = ssum * __expf(m - nm) + ex;
        m = nm;
    }
    float invs = (ssum > 0.f) ? (1.f / ssum) : 0.f;

    // ---- pass 2: weighted gather with 1-deep prefetch ----
    int nq = F >> 7;
    float4 acc4[4];
#pragma unroll
    for (int k = 0; k < 4; k++) acc4[k] = make_float4(0.f, 0.f, 0.f, 0.f);

    int   sCur  = (deg > 0) ? g_csrc[start] : 0;
    float elCur = (deg > 0) ? g_el[sCur * NH + h] : 0.f;
    for (int i = 0; i < deg; i++) {
        int   sNext  = (i + 1 < deg) ? g_csrc[start + i + 1] : 0;
        float elNext = (i + 1 < deg) ? g_el[sNext * NH + h] : 0.f;
        float v = elCur + er_d;
        v = (v > 0.f) ? v : NEG_SLOPE * v;
        float alpha = __expf(v - m) * invs;
        const float4* fp = (const float4*)(feat + ((size_t)sCur * NH + h) * F);
#pragma unroll 4
        for (int k = 0; k < nq; k++) {
            float4 t = fp[lane + 32 * k];
            acc4[k].x = fmaf(t.x, alpha, acc4[k].x);
            acc4[k].y = fmaf(t.y, alpha, acc4[k].y);
            acc4[k].z = fmaf(t.z, alpha, acc4[k].z);
            acc4[k].w = fmaf(t.w, alpha, acc4[k].w);
        }
        sCur = sNext; elCur = elNext;
    }

    float4* op = (float4*)(out + (size_t)warp * F);
    const float4* bp = (const float4*)(bias + h * F);
#pragma unroll 4
    for (int k = 0; k < nq; k++) {
        float4 bb = bp[lane + 32 * k];
        float4 r = acc4[k];
        r.x += bb.x; r.y += bb.y; r.z += bb.z; r.w += bb.w;
        op[lane + 32 * k] = r;
    }
}

// ---------------- GELU (exact) + head mean ----------------
__global__ void k_merge_heads(const float* __restrict__ agg, float* __restrict__ outh, int F) {
    int i = blockIdx.x * blockDim.x + threadIdx.x;
    if (i >= N_NODES * F) return;
    int n = i / F, f = i - n * F;
    float s = 0.f;
#pragma unroll
    for (int h = 0; h < NH; h++) {
        float x = agg[((size_t)n * NH + h) * F + f];
        s += 0.5f * x * (1.f + erff(x * 0.70710678f));
    }
    outh[i] = s * 0.125f;
}

// ---------------- host orchestration ----------------
extern "C" void kernel_launch(void* const* d_in, const int* in_sizes, int n_in,
                              void* d_out, int out_size) {
    const float* node = (const float*)d_in[0];
    const int*   src  = (const int*)d_in[1];
    const int*   dst  = (const int*)d_in[2];
    const float* W1   = (const float*)d_in[3];
    const float* al1  = (const float*)d_in[4];
    const float* ar1  = (const float*)d_in[5];
    const float* b1   = (const float*)d_in[6];
    const float* W2   = (const float*)d_in[7];
    const float* al2  = (const float*)d_in[8];
    const float* ar2  = (const float*)d_in[9];
    const float* b2   = (const float*)d_in[10];
    const float* W3   = (const float*)d_in[11];
    const float* al3  = (const float*)d_in[12];
    const float* ar3  = (const float*)d_in[13];
    const float* b3   = (const float*)d_in[14];
    float* out = (float*)d_out;

    float *feat, *agg, *hbuf;
    __nv_bfloat16 *ahi, *alo, *bhi, *blo;
    cudaGetSymbolAddress((void**)&feat, g_feat);
    cudaGetSymbolAddress((void**)&agg,  g_agg);
    cudaGetSymbolAddress((void**)&hbuf, g_h);
    cudaGetSymbolAddress((void**)&ahi,  g_Ahi);
    cudaGetSymbolAddress((void**)&alo,  g_Alo);
    cudaGetSymbolAddress((void**)&bhi,  g_Bhi);
    cudaGetSymbolAddress((void**)&blo,  g_Blo);

    const int warps = N_NODES * NH;
    const int mtiles = (N_NODES + 127) / 128;

    // slots 1-3, GEMM in slot 4 (ncu capture slot)
    k_zero_cnt<<<(N_NODES + 255) / 256, 256>>>();
    k_split<<<(N_NODES * F_IN / 4 + 255) / 256, 256>>>(node, ahi, alo, N_NODES * F_IN / 4);
    k_transpose_split<<<dim3((NH * F_HID) / 32, F_IN / 32), dim3(32, 8)>>>(W1, bhi, blo, F_IN, NH * F_HID);
    k_gemm_mma<<<dim3((NH * F_HID) / 64, mtiles), 128>>>(ahi, alo, bhi, blo, feat, N_NODES, F_IN, NH * F_HID);

    // CSR build
    k_count<<<(N_EDGES + 255) / 256, 256>>>(dst);
    int nb = (N_NODES + 511) / 512;
    k_scan_block<<<nb, 512>>>();
    k_scan_bsum<<<1, 1>>>(nb);
    k_scan_add<<<nb, 512>>>();
    k_scatter_edges<<<(N_EDGES + 255) / 256, 256>>>(src, dst);

    // layer 1 rest
    k_attn_logits<<<(warps * 32 + 255) / 256, 256>>>(feat, al1, ar1, F_HID);
    k_aggregate_fused<<<(warps * 32 + 255) / 256, 256>>>(feat, b1, agg, F_HID);
    k_merge_heads<<<(N_NODES * F_HID + 255) / 256, 256>>>(agg, hbuf, F_HID);

    // layer 2
    k_split<<<(N_NODES * F_HID / 4 + 255) / 256, 256>>>(hbuf, ahi, alo, N_NODES * F_HID / 4);
    k_transpose_split<<<dim3((NH * F_HID) / 32, F_HID / 32), dim3(32, 8)>>>(W2, bhi, blo, F_HID, NH * F_HID);
    k_gemm_mma<<<dim3((NH * F_HID) / 64, mtiles), 128>>>(ahi, alo, bhi, blo, feat, N_NODES, F_HID, NH * F_HID);
    k_attn_logits<<<(warps * 32 + 255) / 256, 256>>>(feat, al2, ar2, F_HID);
    k_aggregate_fused<<<(warps * 32 + 255) / 256, 256>>>(feat, b2, agg, F_HID);
    k_merge_heads<<<(N_NODES * F_HID + 255) / 256, 256>>>(agg, hbuf, F_HID);

    // layer 3 (aggregate writes d_out directly)
    k_split<<<(N_NODES * F_HID / 4 + 255) / 256, 256>>>(hbuf, ahi, alo, N_NODES * F_HID / 4);
    k_transpose_split<<<dim3((NH * F_OUT) / 32, F_HID / 32), dim3(32, 8)>>>(W3, bhi, blo, F_HID, NH * F_OUT);
    k_gemm_mma<<<dim3((NH * F_OUT) / 64, mtiles), 128>>>(ahi, alo, bhi, blo, feat, N_NODES, F_HID, NH * F_OUT);
    k_attn_logits<<<(warps * 32 + 255) / 256, 256>>>(feat, al3, ar3, F_OUT);
    k_aggregate_fused<<<(warps * 32 + 255) / 256, 256>>>(feat, b3, out, F_OUT);
}

// round 9
// speedup vs baseline: 1.2855x; 1.2004x over previous
#include <cuda_runtime.h>
#include <cuda_bf16.h>
#include <math.h>
#include <stdint.h>

#define N_NODES 20000
#define N_EDGES 160000
#define F_IN   512
#define F_HID  256
#define F_OUT  512
#define NH     8
#define NEG_SLOPE 0.2f

// ---------------- scratch (device globals; allocation-free) ----------------
__device__ float g_feat[(size_t)N_NODES * NH * F_OUT];
__device__ float g_agg [(size_t)N_NODES * NH * F_HID];
__device__ float g_h   [(size_t)N_NODES * F_HID];
__device__ float g_Atf [(size_t)N_NODES * F_IN];     // tf32-rounded A
__device__ float g_Btf [1 << 20];                    // tf32-rounded W^T [Nc,K]
__device__ float g_el  [N_NODES * NH];
__device__ float g_er  [N_NODES * NH];
__device__ int   g_cnt [N_NODES];
__device__ int   g_rs  [N_NODES];
__device__ int   g_cur [N_NODES];
__device__ int   g_csrc[N_EDGES];
__device__ int   g_bsum[64];

// =================== tf32 mma.sync GEMM ===================
// C[M,Nc] = A[M,K] @ W[K,Nc]; inputs pre-rounded to tf32 (fp32 bits).
// Block tile 128x64, BK=32, 4 warps (warp tile 64x32), m16n8k8.tf32.
// Tiles loaded with cp.async.cg (L1-bypassing), fragments via ldmatrix
// (8x4 fp32 subtile == one m8n8.b16 tile).

#define ROWF 144          // smem row stride bytes (9*16B, odd multiple of 16 -> conflict-free)
#define SM_A 0
#define SM_B (128 * ROWF)               // 18432
#define SM_TOT (128 * ROWF + 64 * ROWF) // 27648 B

__device__ __forceinline__ uint32_t smem_u32(const void* p) {
    uint32_t a;
    asm("{ .reg .u64 t; cvta.to.shared.u64 t, %1; cvt.u32.u64 %0, t; }" : "=r"(a) : "l"(p));
    return a;
}
__device__ __forceinline__ void cp_async16(uint32_t dst, const void* src, int src_size) {
    asm volatile("cp.async.cg.shared.global [%0], [%1], 16, %2;"
                 :: "r"(dst), "l"(src), "r"(src_size) : "memory");
}
__device__ __forceinline__ void cp_commit_wait() {
    asm volatile("cp.async.commit_group;" ::: "memory");
    asm volatile("cp.async.wait_group 0;" ::: "memory");
}
__device__ __forceinline__ void ldm_x4(uint32_t* r, uint32_t addr) {
    asm volatile("ldmatrix.sync.aligned.m8n8.x4.shared.b16 {%0,%1,%2,%3}, [%4];"
                 : "=r"(r[0]), "=r"(r[1]), "=r"(r[2]), "=r"(r[3]) : "r"(addr));
}
__device__ __forceinline__ void ldm_x2(uint32_t* r, uint32_t addr) {
    asm volatile("ldmatrix.sync.aligned.m8n8.x2.shared.b16 {%0,%1}, [%2];"
                 : "=r"(r[0]), "=r"(r[1]) : "r"(addr));
}
__device__ __forceinline__ void mma_tf32(float* d, const uint32_t* a, const uint32_t* b) {
    asm volatile(
        "mma.sync.aligned.m16n8k8.row.col.f32.tf32.tf32.f32 "
        "{%0,%1,%2,%3}, {%4,%5,%6,%7}, {%8,%9}, {%0,%1,%2,%3};"
        : "+f"(d[0]), "+f"(d[1]), "+f"(d[2]), "+f"(d[3])
        : "r"(a[0]), "r"(a[1]), "r"(a[2]), "r"(a[3]), "r"(b[0]), "r"(b[1]));
}
__device__ __forceinline__ uint32_t to_tf32(float x) {
    uint32_t r;
    asm("cvt.rna.tf32.f32 %0, %1;" : "=r"(r) : "f"(x));
    return r;
}

__global__ void __launch_bounds__(128) k_gemm_tf32(const float* __restrict__ A,
                                                   const float* __restrict__ B,
                                                   float* __restrict__ C,
                                                   int M, int K, int Nc) {
    __shared__ __align__(16) char sm[SM_TOT];
    const uint32_t smb = smem_u32(sm);

    const int tid  = threadIdx.x;
    const int wid  = tid >> 5;
    const int lane = tid & 31;
    const int m0 = blockIdx.y * 128;
    const int n0 = blockIdx.x * 64;
    const int wm = (wid >> 1) * 64;
    const int wn = (wid & 1) * 32;

    float acc[4][4][4] = {};

    const uint32_t aAddr = smb + SM_A + (wm + (lane & 15)) * ROWF + (lane >> 4) * 16;
    const uint32_t bAddr = smb + SM_B + (wn + (lane & 7)) * ROWF + ((lane >> 3) & 1) * 16;

    // per-thread load mapping (16B units)
    const int lr = tid >> 3;             // 0..15 base row
    const int lc = (tid & 7) * 16;       // byte col 0..112 (32 floats = 128B/row)

    for (int k0 = 0; k0 < K; k0 += 32) {
        if (k0) __syncthreads();
        // ---- A: 128 rows x 32 floats (8 iters of 16 rows) ----
#pragma unroll
        for (int it = 0; it < 8; it++) {
            int r = lr + it * 16;
            int gr = m0 + r;
            const float* src = &A[(size_t)gr * K + k0 + (lc >> 2)];
            cp_async16(smb + SM_A + r * ROWF + lc, src, (gr < M) ? 16 : 0);
        }
        // ---- B: 64 rows x 32 floats (4 iters) ----
#pragma unroll
        for (int it = 0; it < 4; it++) {
            int r = lr + it * 16;
            const float* src = &B[(size_t)(n0 + r) * K + k0 + (lc >> 2)];
            cp_async16(smb + SM_B + r * ROWF + lc, src, 16);
        }
        cp_commit_wait();
        __syncthreads();

        // ---- compute: 4 k-steps of m16n8k8 ----
#pragma unroll
        for (int ks = 0; ks < 4; ks++) {
            uint32_t a[4][4];
#pragma unroll
            for (int mf = 0; mf < 4; mf++)
                ldm_x4(a[mf], aAddr + mf * (16 * ROWF) + ks * 32);
#pragma unroll
            for (int nf = 0; nf < 4; nf++) {
                uint32_t b[2];
                ldm_x2(b, bAddr + nf * (8 * ROWF) + ks * 32);
#pragma unroll
                for (int mf = 0; mf < 4; mf++)
                    mma_tf32(acc[mf][nf], a[mf], b);
            }
        }
    }

    // ---- epilogue ----
#pragma unroll
    for (int mf = 0; mf < 4; mf++) {
        int row0 = m0 + wm + mf * 16 + (lane >> 2);
#pragma unroll
        for (int nf = 0; nf < 4; nf++) {
            int col = n0 + wn + nf * 8 + (lane & 3) * 2;
            if (row0 < M)
                *(float2*)&C[(size_t)row0 * Nc + col] = make_float2(acc[mf][nf][0], acc[mf][nf][1]);
            if (row0 + 8 < M)
                *(float2*)&C[(size_t)(row0 + 8) * Nc + col] = make_float2(acc[mf][nf][2], acc[mf][nf][3]);
        }
    }
}

// ---------------- fp32 -> tf32 rounding pass ----------------
__global__ void k_round_tf32(const float* __restrict__ x, float* __restrict__ y, int n4) {
    int i = blockIdx.x * blockDim.x + threadIdx.x;
    if (i >= n4) return;
    float4 v = ((const float4*)x)[i];
    uint4 o;
    o.x = to_tf32(v.x);
    o.y = to_tf32(v.y);
    o.z = to_tf32(v.z);
    o.w = to_tf32(v.w);
    ((uint4*)y)[i] = o;
}

// ---------------- W transpose + tf32 round: Bt[n][k] = rna(W[k][n]) ----------------
__global__ void k_transpose_tf32(const float* __restrict__ W, float* __restrict__ Bt,
                                 int K, int Nc) {
    __shared__ float tile[32][33];
    int n0 = blockIdx.x * 32, k0 = blockIdx.y * 32;
    int tx = threadIdx.x, ty = threadIdx.y;
#pragma unroll
    for (int j = 0; j < 32; j += 8)
        tile[ty + j][tx] = W[(size_t)(k0 + ty + j) * Nc + n0 + tx];
    __syncthreads();
#pragma unroll
    for (int j = 0; j < 32; j += 8) {
        uint32_t r = to_tf32(tile[tx][ty + j]);
        ((uint32_t*)Bt)[(size_t)(n0 + ty + j) * K + k0 + tx] = r;
    }
}

// ---------------- CSR build ----------------
__global__ void k_zero_cnt() {
    int i = blockIdx.x * blockDim.x + threadIdx.x;
    if (i < N_NODES) g_cnt[i] = 0;
}
__global__ void k_count(const int* __restrict__ dst) {
    int e = blockIdx.x * blockDim.x + threadIdx.x;
    if (e < N_EDGES) atomicAdd(&g_cnt[dst[e]], 1);
}
__global__ void k_scan_block() {
    __shared__ int s[512];
    int i = blockIdx.x * 512 + threadIdx.x;
    int v = (i < N_NODES) ? g_cnt[i] : 0;
    s[threadIdx.x] = v;
    __syncthreads();
    for (int off = 1; off < 512; off <<= 1) {
        int t = (threadIdx.x >= off) ? s[threadIdx.x - off] : 0;
        __syncthreads();
        s[threadIdx.x] += t;
        __syncthreads();
    }
    if (i < N_NODES) g_rs[i] = s[threadIdx.x] - v;
    if (threadIdx.x == 511) g_bsum[blockIdx.x] = s[511];
}
__global__ void k_scan_bsum(int nb) {
    if (threadIdx.x == 0 && blockIdx.x == 0) {
        int acc = 0;
        for (int i = 0; i < nb; i++) { int t = g_bsum[i]; g_bsum[i] = acc; acc += t; }
    }
}
__global__ void k_scan_add() {
    int i = blockIdx.x * 512 + threadIdx.x;
    if (i < N_NODES) {
        int v = g_rs[i] + g_bsum[blockIdx.x];
        g_rs[i]  = v;
        g_cur[i] = v;
    }
}
__global__ void k_scatter_edges(const int* __restrict__ src, const int* __restrict__ dst) {
    int e = blockIdx.x * blockDim.x + threadIdx.x;
    if (e < N_EDGES) {
        int pos = atomicAdd(&g_cur[dst[e]], 1);
        g_csrc[pos] = src[e];
    }
}

// ---------------- attention logits: el/er [N,H] ----------------
__global__ void k_attn_logits(const float* __restrict__ feat,
                              const float* __restrict__ al,
                              const float* __restrict__ ar, int F) {
    int warp = (blockIdx.x * blockDim.x + threadIdx.x) >> 5;
    int lane = threadIdx.x & 31;
    if (warp >= N_NODES * NH) return;
    int h = warp & 7;
    const float4* fp  = (const float4*)(feat + (size_t)warp * F);
    const float4* alp = (const float4*)(al + h * F);
    const float4* arp = (const float4*)(ar + h * F);
    float s1 = 0.f, s2 = 0.f;
    int nq = F >> 2;
    for (int q = lane; q < nq; q += 32) {
        float4 v = fp[q], x = alp[q], y = arp[q];
        s1 = fmaf(v.x, x.x, fmaf(v.y, x.y, fmaf(v.z, x.z, fmaf(v.w, x.w, s1))));
        s2 = fmaf(v.x, y.x, fmaf(v.y, y.y, fmaf(v.z, y.z, fmaf(v.w, y.w, s2))));
    }
#pragma unroll
    for (int o = 16; o; o >>= 1) {
        s1 += __shfl_xor_sync(0xffffffffu, s1, o);
        s2 += __shfl_xor_sync(0xffffffffu, s2, o);
    }
    if (lane == 0) { g_el[warp] = s1; g_er[warp] = s2; }
}

// ---------------- fused edge-softmax + aggregation ----------------
__global__ void k_aggregate_fused(const float* __restrict__ feat,
                                  const float* __restrict__ bias,
                                  float* __restrict__ out, int F) {
    int warp = (blockIdx.x * blockDim.x + threadIdx.x) >> 5;
    int lane = threadIdx.x & 31;
    if (warp >= N_NODES * NH) return;
    int n = warp >> 3, h = warp & 7;

    int start = g_rs[n];
    int deg   = g_cnt[n];
    float er_d = g_er[n * NH + h];

    // ---- pass 1: online softmax ----
    float m = -3.0e38f, ssum = 0.f;
    for (int i0 = 0; i0 < deg; i0 += 32) {
        int i = i0 + lane;
        float e = -3.0e38f;
        if (i < deg) {
            int s = g_csrc[start + i];
            float v = g_el[s * NH + h] + er_d;
            e = (v > 0.f) ? v : NEG_SLOPE * v;
        }
        float cm = e;
#pragma unroll
        for (int o = 16; o; o >>= 1) cm = fmaxf(cm, __shfl_xor_sync(0xffffffffu, cm, o));
        float nm = fmaxf(m, cm);
        float ex = (i < deg) ? __expf(e - nm) : 0.f;
#pragma unroll
        for (int o = 16; o; o >>= 1) ex += __shfl_xor_sync(0xffffffffu, ex, o);
        ssum = ssum * __expf(m - nm) + ex;
        m = nm;
    }
    float invs = (ssum > 0.f) ? (1.f / ssum) : 0.f;

    // ---- pass 2: weighted gather with 1-deep prefetch ----
    int nq = F >> 7;
    float4 acc4[4];
#pragma unroll
    for (int k = 0; k < 4; k++) acc4[k] = make_float4(0.f, 0.f, 0.f, 0.f);

    int   sCur  = (deg > 0) ? g_csrc[start] : 0;
    float elCur = (deg > 0) ? g_el[sCur * NH + h] : 0.f;
    for (int i = 0; i < deg; i++) {
        int   sNext  = (i + 1 < deg) ? g_csrc[start + i + 1] : 0;
        float elNext = (i + 1 < deg) ? g_el[sNext * NH + h] : 0.f;
        float v = elCur + er_d;
        v = (v > 0.f) ? v : NEG_SLOPE * v;
        float alpha = __expf(v - m) * invs;
        const float4* fp = (const float4*)(feat + ((size_t)sCur * NH + h) * F);
#pragma unroll 4
        for (int k = 0; k < nq; k++) {
            float4 t = fp[lane + 32 * k];
            acc4[k].x = fmaf(t.x, alpha, acc4[k].x);
            acc4[k].y = fmaf(t.y, alpha, acc4[k].y);
            acc4[k].z = fmaf(t.z, alpha, acc4[k].z);
            acc4[k].w = fmaf(t.w, alpha, acc4[k].w);
        }
        sCur = sNext; elCur = elNext;
    }

    float4* op = (float4*)(out + (size_t)warp * F);
    const float4* bp = (const float4*)(bias + h * F);
#pragma unroll 4
    for (int k = 0; k < nq; k++) {
        float4 bb = bp[lane + 32 * k];
        float4 r = acc4[k];
        r.x += bb.x; r.y += bb.y; r.z += bb.z; r.w += bb.w;
        op[lane + 32 * k] = r;
    }
}

// ---------------- GELU (exact) + head mean ----------------
__global__ void k_merge_heads(const float* __restrict__ agg, float* __restrict__ outh, int F) {
    int i = blockIdx.x * blockDim.x + threadIdx.x;
    if (i >= N_NODES * F) return;
    int n = i / F, f = i - n * F;
    float s = 0.f;
#pragma unroll
    for (int h = 0; h < NH; h++) {
        float x = agg[((size_t)n * NH + h) * F + f];
        s += 0.5f * x * (1.f + erff(x * 0.70710678f));
    }
    outh[i] = s * 0.125f;
}

// ---------------- host orchestration ----------------
extern "C" void kernel_launch(void* const* d_in, const int* in_sizes, int n_in,
                              void* d_out, int out_size) {
    const float* node = (const float*)d_in[0];
    const int*   src  = (const int*)d_in[1];
    const int*   dst  = (const int*)d_in[2];
    const float* W1   = (const float*)d_in[3];
    const float* al1  = (const float*)d_in[4];
    const float* ar1  = (const float*)d_in[5];
    const float* b1   = (const float*)d_in[6];
    const float* W2   = (const float*)d_in[7];
    const float* al2  = (const float*)d_in[8];
    const float* ar2  = (const float*)d_in[9];
    const float* b2   = (const float*)d_in[10];
    const float* W3   = (const float*)d_in[11];
    const float* al3  = (const float*)d_in[12];
    const float* ar3  = (const float*)d_in[13];
    const float* b3   = (const float*)d_in[14];
    float* out = (float*)d_out;

    float *feat, *agg, *hbuf, *atf, *btf;
    cudaGetSymbolAddress((void**)&feat, g_feat);
    cudaGetSymbolAddress((void**)&agg,  g_agg);
    cudaGetSymbolAddress((void**)&hbuf, g_h);
    cudaGetSymbolAddress((void**)&atf,  g_Atf);
    cudaGetSymbolAddress((void**)&btf,  g_Btf);

    const int warps = N_NODES * NH;
    const int mtiles = (N_NODES + 127) / 128;

    // slots 1-3, GEMM in slot 4 (ncu capture slot)
    k_zero_cnt<<<(N_NODES + 255) / 256, 256>>>();
    k_round_tf32<<<(N_NODES * F_IN / 4 + 255) / 256, 256>>>(node, atf, N_NODES * F_IN / 4);
    k_transpose_tf32<<<dim3((NH * F_HID) / 32, F_IN / 32), dim3(32, 8)>>>(W1, btf, F_IN, NH * F_HID);
    k_gemm_tf32<<<dim3((NH * F_HID) / 64, mtiles), 128>>>(atf, btf, feat, N_NODES, F_IN, NH * F_HID);

    // CSR build
    k_count<<<(N_EDGES + 255) / 256, 256>>>(dst);
    int nb = (N_NODES + 511) / 512;
    k_scan_block<<<nb, 512>>>();
    k_scan_bsum<<<1, 1>>>(nb);
    k_scan_add<<<nb, 512>>>();
    k_scatter_edges<<<(N_EDGES + 255) / 256, 256>>>(src, dst);

    // layer 1 rest
    k_attn_logits<<<(warps * 32 + 255) / 256, 256>>>(feat, al1, ar1, F_HID);
    k_aggregate_fused<<<(warps * 32 + 255) / 256, 256>>>(feat, b1, agg, F_HID);
    k_merge_heads<<<(N_NODES * F_HID + 255) / 256, 256>>>(agg, hbuf, F_HID);

    // layer 2
    k_round_tf32<<<(N_NODES * F_HID / 4 + 255) / 256, 256>>>(hbuf, atf, N_NODES * F_HID / 4);
    k_transpose_tf32<<<dim3((NH * F_HID) / 32, F_HID / 32), dim3(32, 8)>>>(W2, btf, F_HID, NH * F_HID);
    k_gemm_tf32<<<dim3((NH * F_HID) / 64, mtiles), 128>>>(atf, btf, feat, N_NODES, F_HID, NH * F_HID);
    k_attn_logits<<<(warps * 32 + 255) / 256, 256>>>(feat, al2, ar2, F_HID);
    k_aggregate_fused<<<(warps * 32 + 255) / 256, 256>>>(feat, b2, agg, F_HID);
    k_merge_heads<<<(N_NODES * F_HID + 255) / 256, 256>>>(agg, hbuf, F_HID);

    // layer 3 (aggregate writes d_out directly)
    k_round_tf32<<<(N_NODES * F_HID / 4 + 255) / 256, 256>>>(hbuf, atf, N_NODES * F_HID / 4);
    k_transpose_tf32<<<dim3((NH * F_OUT) / 32, F_HID / 32), dim3(32, 8)>>>(W3, btf, F_HID, NH * F_OUT);
    k_gemm_tf32<<<dim3((NH * F_OUT) / 64, mtiles), 128>>>(atf, btf, feat, N_NODES, F_HID, NH * F_OUT);
    k_attn_logits<<<(warps * 32 + 255) / 256, 256>>>(feat, al3, ar3, F_OUT);
    k_aggregate_fused<<<(warps * 32 + 255) / 256, 256>>>(feat, b3, out, F_OUT);
}